// round 9
// baseline (speedup 1.0000x reference)
#include <cuda_runtime.h>
#include <cstdint>

#define NPIX 9216            // H*W = 96*96
#define BATCH 2
#define TOT (BATCH*NPIX)     // 18432
#define RPB 9                // 2048 blocks = 6.92 waves of 296 (2 CTA/SM) -> full-ish last wave
#define NT 512               // threads per block
#define NW (NT/32)           // 16 warps

__device__ float g_p[TOT];   // p = sigmoid(x0-x1)
__device__ float g_a[TOT];   // a = (2p-1)*log2(e)

__device__ __forceinline__ float ex2(float x) {
    float r;
    asm("ex2.approx.ftz.f32 %0, %1;" : "=f"(r) : "f"(x));
    return r;
}

// Kernel 1: per-pixel prep (float4-vectorized), signals dependent launch early.
__global__ void k_prep(const float* __restrict__ x) {
    int i = blockIdx.x * blockDim.x + threadIdx.x;   // quad index
    if (i < TOT / 4) {
        int b = (i * 4) / NPIX;
        int n4 = i - b * (NPIX / 4);
        const float4* x0 = reinterpret_cast<const float4*>(x + (size_t)(b * 2 + 0) * NPIX);
        const float4* x1 = reinterpret_cast<const float4*>(x + (size_t)(b * 2 + 1) * NPIX);
        float4 a = x0[n4], c = x1[n4];
        float4 p, q;
        p.x = 1.0f / (1.0f + __expf(c.x - a.x));
        p.y = 1.0f / (1.0f + __expf(c.y - a.y));
        p.z = 1.0f / (1.0f + __expf(c.z - a.z));
        p.w = 1.0f / (1.0f + __expf(c.w - a.w));
        const float L2E = 1.4426950408889634f;
        q.x = (2.0f * p.x - 1.0f) * L2E;
        q.y = (2.0f * p.y - 1.0f) * L2E;
        q.z = (2.0f * p.z - 1.0f) * L2E;
        q.w = (2.0f * p.w - 1.0f) * L2E;
        reinterpret_cast<float4*>(g_p)[i] = p;
        reinterpret_cast<float4*>(g_a)[i] = q;
    }
    asm volatile("griddepcontrol.launch_dependents;" ::: "memory");
}

// Kernel 2: RPB attention rows per block (512 threads, 18 elems/thread).
//   e_m = 2^(a_r * p_m) ; attn[row,m] = e_m / S ; y[row] fused conv1x1+sigmoid
__global__ void __launch_bounds__(NT, 2)
k_attn(const float* __restrict__ w, const float* __restrict__ cb,
       const float* __restrict__ gm,
       float* __restrict__ y, float* __restrict__ attn) {
    const int tid = threadIdx.x;
    const int lane = tid & 31, wid = tid >> 5;
    const int rowBase = blockIdx.x * RPB;      // 9216 % 9 == 0: no batch straddle
    const int b = rowBase / NPIX;

    __shared__ __align__(16) float sp[NPIX];   // 36 KB p tile
    __shared__ float sS[NW], sT[NW];

    asm volatile("griddepcontrol.wait;" ::: "memory");  // PDL: g_p/g_a ready

    {   // load p tile once per block (L2-resident source)
        const float4* __restrict__ src = reinterpret_cast<const float4*>(g_p + b * NPIX);
        float4* dst = reinterpret_cast<float4*>(sp);
#pragma unroll
        for (int k = 0; k < NPIX / 4 / NT; k++)         // 4 iters + remainder
            dst[tid + k * NT] = src[tid + k * NT];
        if (tid < (NPIX / 4) - (NPIX / 4 / NT) * NT)    // 256 leftover float4
            dst[tid + (NPIX / 4 / NT) * NT] = src[tid + (NPIX / 4 / NT) * NT];
    }
    __syncthreads();

    const float2* sp2 = reinterpret_cast<const float2*>(sp);

#pragma unroll 1
    for (int r = 0; r < RPB; r++) {
        const int row = rowBase + r;
        const float a2 = g_a[row];             // L2 hit, broadcast

        float E[18];                   // full e cache: store phase = FMUL+STG only
        float S = 0.0f, T = 0.0f;
#pragma unroll
        for (int k = 0; k < 9; k++) {          // 9 x float2 = 18 elems/thread
            float2 pv = sp2[tid + k * NT];
            float e0 = ex2(a2 * pv.x);
            float e1 = ex2(a2 * pv.y);
            E[2*k+0] = e0; E[2*k+1] = e1;
            S += e0 + e1;
            T = fmaf(pv.x, e0, T);
            T = fmaf(pv.y, e1, T);
        }

        // block reduce S, T (16 warps)
#pragma unroll
        for (int o = 16; o > 0; o >>= 1) {
            S += __shfl_xor_sync(0xFFFFFFFFu, S, o);
            T += __shfl_xor_sync(0xFFFFFFFFu, T, o);
        }
        __syncthreads();               // protect sS/sT reuse across rows
        if (lane == 0) { sS[wid] = S; sT[wid] = T; }
        __syncthreads();
        float St = 0.0f;
#pragma unroll
        for (int i = 0; i < NW; i++) St += sS[i];
        float invS = 1.0f / St;

        if (tid == 0) {                // fused conv1x1 + sigmoid epilogue
            float Tt = 0.0f;
#pragma unroll
            for (int i = 0; i < NW; i++) Tt += sT[i];
            float o0 = Tt * invS;
            float p  = sp[row - b * NPIX];
            float g  = gm[0];
            float pre0 = fmaf(g, o0, p);
            float pre1 = fmaf(g, 1.0f - o0, 1.0f - p);
            float t = fmaf(w[0], pre0, fmaf(w[1], pre1, cb[0]));
            y[row] = 1.0f / (1.0f + __expf(-t));
        }

        float2* __restrict__ out2 =
            reinterpret_cast<float2*>(attn + (size_t)row * NPIX);
#pragma unroll
        for (int k = 0; k < 9; k++) {
            float2 o;
            o.x = E[2*k+0] * invS;
            o.y = E[2*k+1] * invS;
            out2[tid + k * NT] = o;    // coalesced 256B/warp streaming stores
        }
    }
}

extern "C" void kernel_launch(void* const* d_in, const int* in_sizes, int n_in,
                              void* d_out, int out_size) {
    const float* x  = (const float*)d_in[0];   // [2,2,96,96]
    const float* w  = (const float*)d_in[1];   // [2]
    const float* cb = (const float*)d_in[2];   // [1]
    const float* gm = (const float*)d_in[3];   // [1]
    float* out = (float*)d_out;                // [18432 y | 2*9216*9216 attn]
    float* yp = out;
    float* attn = out + TOT;

    k_prep<<<(TOT / 4 + 255) / 256, 256>>>(x);

    // k_attn with Programmatic Dependent Launch (overlaps launch ramp w/ prep)
    cudaLaunchConfig_t cfg = {};
    cfg.gridDim  = dim3(TOT / RPB, 1, 1);
    cfg.blockDim = dim3(NT, 1, 1);
    cfg.dynamicSmemBytes = 0;
    cfg.stream = 0;
    cudaLaunchAttribute attr[1];
    attr[0].id = cudaLaunchAttributeProgrammaticStreamSerialization;
    attr[0].val.programmaticStreamSerializationAllowed = 1;
    cfg.attrs = attr;
    cfg.numAttrs = 1;
    cudaLaunchKernelEx(&cfg, k_attn, w, cb, gm, yp, attn);
}

// round 10
// speedup vs baseline: 1.0940x; 1.0940x over previous
#include <cuda_runtime.h>
#include <cstdint>

#define NPIX 9216            // H*W = 96*96
#define BATCH 2
#define TOT (BATCH*NPIX)     // 18432
#define RPB 8                // 2304 blocks = 3.89 waves of 592 (4 CTA/SM)

__device__ float g_p[TOT];   // p = sigmoid(x0-x1)
__device__ float g_a[TOT];   // a = (2p-1)*log2(e)

__device__ __forceinline__ float ex2(float x) {
    float r;
    asm("ex2.approx.ftz.f32 %0, %1;" : "=f"(r) : "f"(x));
    return r;
}
__device__ __forceinline__ float lg2(float x) {
    float r;
    asm("lg2.approx.ftz.f32 %0, %1;" : "=f"(r) : "f"(x));
    return r;
}

// Kernel 1: per-pixel prep (float4-vectorized), signals dependent launch early.
__global__ void k_prep(const float* __restrict__ x) {
    int i = blockIdx.x * blockDim.x + threadIdx.x;   // quad index
    if (i < TOT / 4) {
        int b = (i * 4) / NPIX;
        int n4 = i - b * (NPIX / 4);
        const float4* x0 = reinterpret_cast<const float4*>(x + (size_t)(b * 2 + 0) * NPIX);
        const float4* x1 = reinterpret_cast<const float4*>(x + (size_t)(b * 2 + 1) * NPIX);
        float4 a = x0[n4], c = x1[n4];
        float4 p, q;
        p.x = 1.0f / (1.0f + __expf(c.x - a.x));
        p.y = 1.0f / (1.0f + __expf(c.y - a.y));
        p.z = 1.0f / (1.0f + __expf(c.z - a.z));
        p.w = 1.0f / (1.0f + __expf(c.w - a.w));
        const float L2E = 1.4426950408889634f;
        q.x = (2.0f * p.x - 1.0f) * L2E;
        q.y = (2.0f * p.y - 1.0f) * L2E;
        q.z = (2.0f * p.z - 1.0f) * L2E;
        q.w = (2.0f * p.w - 1.0f) * L2E;
        reinterpret_cast<float4*>(g_p)[i] = p;
        reinterpret_cast<float4*>(g_a)[i] = q;
    }
    asm volatile("griddepcontrol.launch_dependents;" ::: "memory");
}

// Kernel 2: RPB attention rows per block (256 threads, 4 CTAs/SM).
//   attn[row,m] = 2^(a_r p_m - log2 S_r)   (normalization folded into exponent;
//   no per-thread e cache -> low regs -> high occupancy with STG.128 stores)
__global__ void __launch_bounds__(256, 4)
k_attn(const float* __restrict__ w, const float* __restrict__ cb,
       const float* __restrict__ gm,
       float* __restrict__ y, float* __restrict__ attn) {
    const int tid = threadIdx.x;
    const int lane = tid & 31, wid = tid >> 5;
    const int rowBase = blockIdx.x * RPB;      // 9216 % 8 == 0: no batch straddle
    const int b = rowBase / NPIX;

    __shared__ __align__(16) float sp[NPIX];   // 36 KB p tile
    __shared__ float sS[8], sT[8];

    asm volatile("griddepcontrol.wait;" ::: "memory");  // PDL: g_p/g_a ready

    {   // load p tile once per block (L2-resident source)
        const float4* __restrict__ src = reinterpret_cast<const float4*>(g_p + b * NPIX);
        float4* dst = reinterpret_cast<float4*>(sp);
#pragma unroll
        for (int k = 0; k < 9; k++)
            dst[tid + k * 256] = src[tid + k * 256];
    }
    __syncthreads();

    const float4* sp4 = reinterpret_cast<const float4*>(sp);

#pragma unroll 1
    for (int r = 0; r < RPB; r++) {
        const int row = rowBase + r;
        const float a2 = g_a[row];             // L2 hit, broadcast

        // Pass 1: reduce S = sum 2^(a p), T = sum p 2^(a p)
        float S = 0.0f, T = 0.0f;
#pragma unroll
        for (int k = 0; k < 9; k++) {
            float4 pv = sp4[tid + k * 256];
            float e0 = ex2(a2 * pv.x);
            float e1 = ex2(a2 * pv.y);
            float e2 = ex2(a2 * pv.z);
            float e3 = ex2(a2 * pv.w);
            S += (e0 + e1) + (e2 + e3);
            T = fmaf(pv.x, e0, T); T = fmaf(pv.y, e1, T);
            T = fmaf(pv.z, e2, T); T = fmaf(pv.w, e3, T);
        }
#pragma unroll
        for (int o = 16; o > 0; o >>= 1) {
            S += __shfl_xor_sync(0xFFFFFFFFu, S, o);
            T += __shfl_xor_sync(0xFFFFFFFFu, T, o);
        }
        __syncthreads();               // protect sS/sT reuse across rows
        if (lane == 0) { sS[wid] = S; sT[wid] = T; }
        __syncthreads();
        float St = ((sS[0]+sS[1]) + (sS[2]+sS[3])) + ((sS[4]+sS[5]) + (sS[6]+sS[7]));
        const float c2 = -lg2(St);     // fold 1/S into the exponent

        if (tid == 0) {                // fused conv1x1 + sigmoid epilogue
            float Tt = ((sT[0]+sT[1]) + (sT[2]+sT[3])) + ((sT[4]+sT[5]) + (sT[6]+sT[7]));
            float o0 = Tt / St;
            float p  = sp[row - b * NPIX];
            float g  = gm[0];
            float pre0 = fmaf(g, o0, p);
            float pre1 = fmaf(g, 1.0f - o0, 1.0f - p);
            float t = fmaf(w[0], pre0, fmaf(w[1], pre1, cb[0]));
            y[row] = 1.0f / (1.0f + __expf(-t));
        }

        // Pass 2: store 2^(a p + c) directly (FMA+MUFU -> STG.128)
        float4* __restrict__ out4 =
            reinterpret_cast<float4*>(attn + (size_t)row * NPIX);
#pragma unroll
        for (int k = 0; k < 9; k++) {
            float4 pv = sp4[tid + k * 256];
            float4 o;
            o.x = ex2(fmaf(a2, pv.x, c2));
            o.y = ex2(fmaf(a2, pv.y, c2));
            o.z = ex2(fmaf(a2, pv.z, c2));
            o.w = ex2(fmaf(a2, pv.w, c2));
            out4[tid + k * 256] = o;   // coalesced 128-bit streaming stores
        }
    }
}

extern "C" void kernel_launch(void* const* d_in, const int* in_sizes, int n_in,
                              void* d_out, int out_size) {
    const float* x  = (const float*)d_in[0];   // [2,2,96,96]
    const float* w  = (const float*)d_in[1];   // [2]
    const float* cb = (const float*)d_in[2];   // [1]
    const float* gm = (const float*)d_in[3];   // [1]
    float* out = (float*)d_out;                // [18432 y | 2*9216*9216 attn]
    float* yp = out;
    float* attn = out + TOT;

    k_prep<<<(TOT / 4 + 255) / 256, 256>>>(x);

    // k_attn with Programmatic Dependent Launch (overlaps launch ramp w/ prep)
    cudaLaunchConfig_t cfg = {};
    cfg.gridDim  = dim3(TOT / RPB, 1, 1);
    cfg.blockDim = dim3(256, 1, 1);
    cfg.dynamicSmemBytes = 0;
    cfg.stream = 0;
    cudaLaunchAttribute attr[1];
    attr[0].id = cudaLaunchAttributeProgrammaticStreamSerialization;
    attr[0].val.programmaticStreamSerializationAllowed = 1;
    cfg.attrs = attr;
    cfg.numAttrs = 1;
    cudaLaunchKernelEx(&cfg, k_attn, w, cb, gm, yp, attn);
}

// round 11
// speedup vs baseline: 1.1119x; 1.0164x over previous
#include <cuda_runtime.h>
#include <cstdint>

#define NPIX 9216            // H*W = 96*96
#define BATCH 2
#define TOT (BATCH*NPIX)     // 18432
#define RPB 8                // rows per block (2304 blocks)
#define RB 4                 // rows per merged batch

__device__ float g_p[TOT];   // p = sigmoid(x0-x1)
__device__ float g_a[TOT];   // a = (2p-1)*log2(e)

__device__ __forceinline__ float ex2(float x) {
    float r;
    asm("ex2.approx.ftz.f32 %0, %1;" : "=f"(r) : "f"(x));
    return r;
}
__device__ __forceinline__ float lg2(float x) {
    float r;
    asm("lg2.approx.ftz.f32 %0, %1;" : "=f"(r) : "f"(x));
    return r;
}

// Kernel 1: per-pixel prep (float4-vectorized), signals dependent launch early.
__global__ void k_prep(const float* __restrict__ x) {
    int i = blockIdx.x * blockDim.x + threadIdx.x;   // quad index
    if (i < TOT / 4) {
        int b = (i * 4) / NPIX;
        int n4 = i - b * (NPIX / 4);
        const float4* x0 = reinterpret_cast<const float4*>(x + (size_t)(b * 2 + 0) * NPIX);
        const float4* x1 = reinterpret_cast<const float4*>(x + (size_t)(b * 2 + 1) * NPIX);
        float4 a = x0[n4], c = x1[n4];
        float4 p, q;
        p.x = 1.0f / (1.0f + __expf(c.x - a.x));
        p.y = 1.0f / (1.0f + __expf(c.y - a.y));
        p.z = 1.0f / (1.0f + __expf(c.z - a.z));
        p.w = 1.0f / (1.0f + __expf(c.w - a.w));
        const float L2E = 1.4426950408889634f;
        q.x = (2.0f * p.x - 1.0f) * L2E;
        q.y = (2.0f * p.y - 1.0f) * L2E;
        q.z = (2.0f * p.z - 1.0f) * L2E;
        q.w = (2.0f * p.w - 1.0f) * L2E;
        reinterpret_cast<float4*>(g_p)[i] = p;
        reinterpret_cast<float4*>(g_a)[i] = q;
    }
    asm volatile("griddepcontrol.launch_dependents;" ::: "memory");
}

// Kernel 2: rows processed in batches of RB. Compute phase evaluates all RB
// rows per p-element (1 LDS feeds RB*4 exps); store phase is k-outer with RB
// independent row streams per step. attn[row,m] = 2^(a_r p_m - log2 S_r).
__global__ void __launch_bounds__(256, 3)
k_attn(const float* __restrict__ w, const float* __restrict__ cb,
       const float* __restrict__ gm,
       float* __restrict__ y, float* __restrict__ attn) {
    const int tid = threadIdx.x;
    const int lane = tid & 31, wid = tid >> 5;
    const int rowBase = blockIdx.x * RPB;      // 9216 % 8 == 0: no batch straddle
    const int b = rowBase / NPIX;

    __shared__ __align__(16) float sp[NPIX];   // 36 KB p tile
    __shared__ float sS[2][8 * RB], sT[2][8 * RB];   // double-buffered reductions

    asm volatile("griddepcontrol.wait;" ::: "memory");  // PDL: g_p/g_a ready

    {   // load p tile once per block (L2-resident source)
        const float4* __restrict__ src = reinterpret_cast<const float4*>(g_p + b * NPIX);
        float4* dst = reinterpret_cast<float4*>(sp);
#pragma unroll
        for (int k = 0; k < 9; k++)
            dst[tid + k * 256] = src[tid + k * 256];
    }
    __syncthreads();

    const float4* sp4 = reinterpret_cast<const float4*>(sp);

#pragma unroll 1
    for (int bt = 0; bt < RPB / RB; bt++) {
        const int row0 = rowBase + bt * RB;
        const int buf = bt & 1;

        float a2[RB];
#pragma unroll
        for (int r = 0; r < RB; r++) a2[r] = g_a[row0 + r];   // L2 hits

        // ---- compute phase: all RB rows per p element ----
        float S[RB], T[RB];
#pragma unroll
        for (int r = 0; r < RB; r++) { S[r] = 0.0f; T[r] = 0.0f; }
#pragma unroll
        for (int k = 0; k < 9; k++) {
            float4 pv = sp4[tid + k * 256];
#pragma unroll
            for (int r = 0; r < RB; r++) {
                float e0 = ex2(a2[r] * pv.x);
                float e1 = ex2(a2[r] * pv.y);
                float e2 = ex2(a2[r] * pv.z);
                float e3 = ex2(a2[r] * pv.w);
                S[r] += (e0 + e1) + (e2 + e3);
                T[r] = fmaf(pv.x, e0, T[r]); T[r] = fmaf(pv.y, e1, T[r]);
                T[r] = fmaf(pv.z, e2, T[r]); T[r] = fmaf(pv.w, e3, T[r]);
            }
        }

        // ---- block reduce RB x (S,T) ----
#pragma unroll
        for (int o = 16; o > 0; o >>= 1) {
#pragma unroll
            for (int r = 0; r < RB; r++) {
                S[r] += __shfl_xor_sync(0xFFFFFFFFu, S[r], o);
                T[r] += __shfl_xor_sync(0xFFFFFFFFu, T[r], o);
            }
        }
        if (lane == 0) {
#pragma unroll
            for (int r = 0; r < RB; r++) {
                sS[buf][wid * RB + r] = S[r];
                sT[buf][wid * RB + r] = T[r];
            }
        }
        __syncthreads();               // single barrier per batch (double-buffered)

        float c2[RB];
#pragma unroll
        for (int r = 0; r < RB; r++) {
            float St = 0.0f;
#pragma unroll
            for (int i = 0; i < 8; i++) St += sS[buf][i * RB + r];
            c2[r] = -lg2(St);          // fold 1/S into exponent
        }

        if (tid < RB) {                // fused conv1x1 + sigmoid epilogue (1 thread/row)
            const int r = tid;
            float St = 0.0f, Tt = 0.0f;
#pragma unroll
            for (int i = 0; i < 8; i++) { St += sS[buf][i * RB + r]; Tt += sT[buf][i * RB + r]; }
            float o0 = Tt / St;
            float p  = sp[row0 + r - b * NPIX];
            float g  = gm[0];
            float pre0 = fmaf(g, o0, p);
            float pre1 = fmaf(g, 1.0f - o0, 1.0f - p);
            float t = fmaf(w[0], pre0, fmaf(w[1], pre1, cb[0]));
            y[row0 + r] = 1.0f / (1.0f + __expf(-t));
        }

        // ---- store phase: k-outer, RB independent row streams ----
        float4* __restrict__ o0p = reinterpret_cast<float4*>(attn + (size_t)(row0 + 0) * NPIX);
        float4* __restrict__ o1p = reinterpret_cast<float4*>(attn + (size_t)(row0 + 1) * NPIX);
        float4* __restrict__ o2p = reinterpret_cast<float4*>(attn + (size_t)(row0 + 2) * NPIX);
        float4* __restrict__ o3p = reinterpret_cast<float4*>(attn + (size_t)(row0 + 3) * NPIX);
        float4* outp[RB] = {o0p, o1p, o2p, o3p};
#pragma unroll
        for (int k = 0; k < 9; k++) {
            float4 pv = sp4[tid + k * 256];
            const int off = tid + k * 256;
#pragma unroll
            for (int r = 0; r < RB; r++) {
                float4 o;
                o.x = ex2(fmaf(a2[r], pv.x, c2[r]));
                o.y = ex2(fmaf(a2[r], pv.y, c2[r]));
                o.z = ex2(fmaf(a2[r], pv.z, c2[r]));
                o.w = ex2(fmaf(a2[r], pv.w, c2[r]));
                outp[r][off] = o;      // 4 independent coalesced streams
            }
        }
    }
}

extern "C" void kernel_launch(void* const* d_in, const int* in_sizes, int n_in,
                              void* d_out, int out_size) {
    const float* x  = (const float*)d_in[0];   // [2,2,96,96]
    const float* w  = (const float*)d_in[1];   // [2]
    const float* cb = (const float*)d_in[2];   // [1]
    const float* gm = (const float*)d_in[3];   // [1]
    float* out = (float*)d_out;                // [18432 y | 2*9216*9216 attn]
    float* yp = out;
    float* attn = out + TOT;

    k_prep<<<(TOT / 4 + 255) / 256, 256>>>(x);

    // k_attn with Programmatic Dependent Launch (overlaps launch ramp w/ prep)
    cudaLaunchConfig_t cfg = {};
    cfg.gridDim  = dim3(TOT / RPB, 1, 1);
    cfg.blockDim = dim3(256, 1, 1);
    cfg.dynamicSmemBytes = 0;
    cfg.stream = 0;
    cudaLaunchAttribute attr[1];
    attr[0].id = cudaLaunchAttributeProgrammaticStreamSerialization;
    attr[0].val.programmaticStreamSerializationAllowed = 1;
    cfg.attrs = attr;
    cfg.numAttrs = 1;
    cudaLaunchKernelEx(&cfg, k_attn, w, cb, gm, yp, attn);
}